// round 16
// baseline (speedup 1.0000x reference)
#include <cuda_runtime.h>
#include <cuda_fp16.h>
#include <cstdint>
#include <math.h>

#define BATCH 4
#define SEQ   2048
#define HID   2048
#define INTER 5504
#define MTOK  (BATCH*SEQ)            // 8192
#define OUT_ELEMS ((long)MTOK*HID)   // 16777216

// ---------------- scratch ----------------
__device__ __half g_Xh [(long)MTOK*HID];
__device__ __half g_Wgh[(long)INTER*HID];
__device__ __half g_Wuh[(long)INTER*HID];
__device__ __half g_Wdh[(long)HID*INTER];
__device__ __half g_inter[(long)MTOK*INTER];
__device__ float  g_rowsq[INTER];
__device__ float  g_s[BATCH*INTER];      // impacts accumulator (atomicAdd)

// ---------------- helpers ----------------
__device__ __forceinline__ uint32_t smem_u32(const void* p){
    uint32_t a;
    asm("{ .reg .u64 t; cvta.to.shared.u64 t, %1; cvt.u32.u64 %0, t; }" : "=r"(a) : "l"(p));
    return a;
}
__device__ __forceinline__ void cpa16(uint32_t dst, const void* src){
    asm volatile("cp.async.cg.shared.global [%0], [%1], 16;" :: "r"(dst), "l"(src));
}
__device__ __forceinline__ void ldsm4(uint32_t r[4], uint32_t addr){
    asm volatile("ldmatrix.sync.aligned.m8n8.x4.shared.b16 {%0,%1,%2,%3}, [%4];"
                 : "=r"(r[0]), "=r"(r[1]), "=r"(r[2]), "=r"(r[3]) : "r"(addr));
}
__device__ __forceinline__ void mma_f16(float c[4],
                                        uint32_t a0, uint32_t a1, uint32_t a2, uint32_t a3,
                                        uint32_t b0, uint32_t b1) {
    asm volatile(
        "mma.sync.aligned.m16n8k16.row.col.f32.f16.f16.f32 "
        "{%0,%1,%2,%3}, {%4,%5,%6,%7}, {%8,%9}, {%0,%1,%2,%3};"
        : "+f"(c[0]), "+f"(c[1]), "+f"(c[2]), "+f"(c[3])
        : "r"(a0), "r"(a1), "r"(a2), "r"(a3), "r"(b0), "r"(b1));
}
#define CP_COMMIT() asm volatile("cp.async.commit_group;" ::: "memory")
#define CP_WAIT(n)  asm volatile("cp.async.wait_group %0;" :: "n"(n) : "memory")

// 128B-row XOR swizzle (conflict-free)
#define SWZB(o) ((o) ^ (((o) >> 3) & 0x70))

// ============================================================================
// Fused gate/up GEMM + SwiGLU + impacts partials (R13-proven math).
// Chunked: one launch covers ONE group g of 16 row-blocks (grid = 86*16 = 1376).
// Block 128m x 64n, 8 warps; 3 stages x 32KB = 96KB -> 2 CTAs/SM; unroll-3.
// ============================================================================
#define GU_STAGE_B 32768
#define GU_BG_OFF  16384
#define GU_BU_OFF  24576
#define GU_SMEM_BYTES (3*GU_STAGE_B)   // 98304

__global__ void __launch_bounds__(256,2)
gemm_gu(const __half* __restrict__ X, const __half* __restrict__ Wg,
        const __half* __restrict__ Wu, __half* __restrict__ inter,
        float* __restrict__ spart, int gbase)
{
    extern __shared__ char smemc[];
    const uint32_t sb = smem_u32(smemc);

    const int tid  = threadIdx.x;
    const int wid  = tid >> 5;
    const int lane = tid & 31;
    const int grp  = lane >> 2;
    const int tig  = lane & 3;
    const int wm   = wid >> 2;    // 0..1
    const int wn   = wid & 3;     // 0..3

    const int GM  = 16;
    int r = blockIdx.x;
    const long bm = (long)(gbase*GM + (r % GM)) * 128;
    const int  bn = (r / GM) * 64;

    const int ldr = tid >> 3;        // 0..31
    const int ldc = tid & 7;         // 0..7 (16B units)

    const __half* Ag = X  + (bm + ldr)*(long)HID + ldc*8;
    const __half* Gg = Wg + (long)(bn + ldr)*HID + ldc*8;
    const __half* Ug = Wu + (long)(bn + ldr)*HID + ldc*8;

    float acc_g[4][2][4], acc_u[4][2][4];
#pragma unroll
    for (int mi = 0; mi < 4; mi++)
#pragma unroll
        for (int ni = 0; ni < 2; ni++)
#pragma unroll
            for (int q = 0; q < 4; q++) { acc_g[mi][ni][q] = 0.f; acc_u[mi][ni][q] = 0.f; }

    uint32_t stoffA[4];
#pragma unroll
    for (int i = 0; i < 4; i++)
        stoffA[i] = SWZB((uint32_t)((ldr + 32*i)*128 + ldc*16));
    uint32_t stoffB[2];
#pragma unroll
    for (int i = 0; i < 2; i++)
        stoffB[i] = SWZB((uint32_t)((ldr + 32*i)*128 + ldc*16));

    const uint32_t swzm = (lane & 7) * 16;
    const uint32_t browA = (wm*64 + (lane & 15)) * 128;
    const uint32_t akbe = ((lane >> 4) & 1) * 16;
    const uint32_t browB = (wn*16 + ((lane >> 4) & 1)*8 + (lane & 7)) * 128;
    const uint32_t bkbe = ((lane >> 3) & 1) * 16;
    uint32_t akb_r[4], bkb_r[4];
#pragma unroll
    for (int ks = 0; ks < 4; ks++) {
        akb_r[ks] = ((uint32_t)(ks*32) + akbe) ^ swzm;
        bkb_r[ks] = ((uint32_t)(ks*32) + bkbe) ^ swzm;
    }

    const int nK = HID/64;   // 32

#pragma unroll
    for (int p = 0; p < 2; p++) {
        const int k0 = p*64;
        const uint32_t st = sb + p*GU_STAGE_B;
#pragma unroll
        for (int i = 0; i < 4; i++)
            cpa16(st + stoffA[i], Ag + (long)i*32*HID + k0);
#pragma unroll
        for (int i = 0; i < 2; i++) {
            cpa16(st + GU_BG_OFF + stoffB[i], Gg + (long)i*32*HID + k0);
            cpa16(st + GU_BU_OFF + stoffB[i], Ug + (long)i*32*HID + k0);
        }
        CP_COMMIT();
    }

#define GU_BODY(SS)                                                            \
    {                                                                          \
        CP_WAIT(1);                                                            \
        __syncthreads();                                                       \
        if (j + 2 < nK) {                                                      \
            const int k0 = (j+2)*64;                                           \
            const uint32_t st = sb + (((SS)+2)%3)*GU_STAGE_B;                  \
            _Pragma("unroll")                                                  \
            for (int i = 0; i < 4; i++)                                        \
                cpa16(st + stoffA[i], Ag + (long)i*32*HID + k0);               \
            _Pragma("unroll")                                                  \
            for (int i = 0; i < 2; i++) {                                      \
                cpa16(st + GU_BG_OFF + stoffB[i], Gg + (long)i*32*HID + k0);   \
                cpa16(st + GU_BU_OFF + stoffB[i], Ug + (long)i*32*HID + k0);   \
            }                                                                  \
        }                                                                      \
        CP_COMMIT();                                                           \
        const uint32_t As = sb + (SS)*GU_STAGE_B;                              \
        const uint32_t Gs = As + GU_BG_OFF;                                    \
        const uint32_t Us = As + GU_BU_OFF;                                    \
        _Pragma("unroll")                                                      \
        for (int ks = 0; ks < 4; ks++) {                                       \
            uint32_t af[4][4], bg[4], bu[4];                                   \
            _Pragma("unroll")                                                  \
            for (int mi = 0; mi < 4; mi++)                                     \
                ldsm4(af[mi], As + browA + mi*2048 + akb_r[ks]);               \
            ldsm4(bg, Gs + browB + bkb_r[ks]);                                 \
            ldsm4(bu, Us + browB + bkb_r[ks]);                                 \
            _Pragma("unroll")                                                  \
            for (int mi = 0; mi < 4; mi++)                                     \
                _Pragma("unroll")                                              \
                for (int ni = 0; ni < 2; ni++) {                               \
                    mma_f16(acc_g[mi][ni], af[mi][0], af[mi][1], af[mi][2],    \
                            af[mi][3], bg[ni*2], bg[ni*2+1]);                  \
                    mma_f16(acc_u[mi][ni], af[mi][0], af[mi][1], af[mi][2],    \
                            af[mi][3], bu[ni*2], bu[ni*2+1]);                  \
                }                                                              \
        }                                                                      \
        j++;                                                                   \
    }

    {
        int j = 0;
        while (j + 3 <= nK) { GU_BODY(0); GU_BODY(1); GU_BODY(2); }
        GU_BODY(0); GU_BODY(1);   // 32 = 3*10 + 2
    }
#undef GU_BODY

    float cs[2][2] = {{0.f,0.f},{0.f,0.f}};
#pragma unroll
    for (int mi = 0; mi < 4; mi++) {
#pragma unroll
        for (int ni = 0; ni < 2; ni++) {
            long r0 = bm + wm*64 + mi*16 + grp;
            long c0 = bn + wn*16 + ni*8 + tig*2;
            float gv, uv; __half2 h;
            gv = acc_g[mi][ni][0]; uv = acc_u[mi][ni][0];
            float o0 = (gv / (1.f + __expf(-gv))) * uv;
            gv = acc_g[mi][ni][1]; uv = acc_u[mi][ni][1];
            float o1 = (gv / (1.f + __expf(-gv))) * uv;
            h = __floats2half2_rn(o0, o1);
            *(__half2*)(inter + r0*INTER + c0) = h;
            gv = acc_g[mi][ni][2]; uv = acc_u[mi][ni][2];
            float o2 = (gv / (1.f + __expf(-gv))) * uv;
            gv = acc_g[mi][ni][3]; uv = acc_u[mi][ni][3];
            float o3 = (gv / (1.f + __expf(-gv))) * uv;
            h = __floats2half2_rn(o2, o3);
            *(__half2*)(inter + (r0+8)*INTER + c0) = h;
            cs[ni][0] += o0*o0 + o2*o2;
            cs[ni][1] += o1*o1 + o3*o3;
        }
    }
#pragma unroll
    for (int off = 4; off < 32; off <<= 1) {
#pragma unroll
        for (int ni = 0; ni < 2; ni++) {
            cs[ni][0] += __shfl_xor_sync(0xffffffffu, cs[ni][0], off);
            cs[ni][1] += __shfl_xor_sync(0xffffffffu, cs[ni][1], off);
        }
    }
    if (grp == 0) {
        const int b = (int)(bm >> 11);
        float* sp = spart + b*INTER;
#pragma unroll
        for (int ni = 0; ni < 2; ni++) {
            int c0 = bn + wn*16 + ni*8 + tig*2;
            atomicAdd(&sp[c0],   cs[ni][0]);
            atomicAdd(&sp[c0+1], cs[ni][1]);
        }
    }
}

// ============================================================================
// Down GEMM (R10-proven math), chunked: one launch = one group g of 16
// row-blocks (grid = 16*16 = 256). Block 128x128; 96KB; 2 CTAs/SM; unroll-3.
// ============================================================================
#define DN_STAGE_B 32768
#define DN_B_OFF   16384
#define DN_SMEM_BYTES (3*DN_STAGE_B)   // 98304

__global__ void __launch_bounds__(256,2)
gemm_down(const __half* __restrict__ A, const __half* __restrict__ B, float* __restrict__ C,
          int gbase)
{
    extern __shared__ char smemc[];
    const uint32_t sb = smem_u32(smemc);

    const int tid  = threadIdx.x;
    const int wid  = tid >> 5;
    const int lane = tid & 31;
    const int grp  = lane >> 2;
    const int tig  = lane & 3;
    const int wm   = wid >> 2;
    const int wn   = wid & 3;

    const int GM  = 16;
    int r = blockIdx.x;
    const long bm = (long)(gbase*GM + (r % GM)) * 128;
    const int  bn = (r / GM) * 128;

    const int ldr = tid >> 3;
    const int ldc = tid & 7;

    const __half* Ag = A + (bm + ldr)*(long)INTER + ldc*8;
    const __half* Bg = B + (long)(bn + ldr)*INTER + ldc*8;

    float acc[4][4][4];
#pragma unroll
    for (int mi = 0; mi < 4; mi++)
#pragma unroll
        for (int ni = 0; ni < 4; ni++)
#pragma unroll
            for (int q = 0; q < 4; q++) acc[mi][ni][q] = 0.f;

    uint32_t stoff[4];
#pragma unroll
    for (int i = 0; i < 4; i++)
        stoff[i] = SWZB((uint32_t)((ldr + 32*i)*128 + ldc*16));

    const uint32_t swzm = (lane & 7) * 16;
    const uint32_t browA = (wm*64 + (lane & 15)) * 128;
    const uint32_t akbe = ((lane >> 4) & 1) * 16;
    const uint32_t browB = (wn*32 + ((lane >> 4) & 1)*8 + (lane & 7)) * 128;
    const uint32_t bkbe = ((lane >> 3) & 1) * 16;
    uint32_t akb_r[4], bkb_r[4];
#pragma unroll
    for (int ks = 0; ks < 4; ks++) {
        akb_r[ks] = ((uint32_t)(ks*32) + akbe) ^ swzm;
        bkb_r[ks] = ((uint32_t)(ks*32) + bkbe) ^ swzm;
    }

    const int nK = INTER/64;   // 86

#pragma unroll
    for (int p = 0; p < 2; p++) {
        const int k0 = p*64;
        const uint32_t st = sb + p*DN_STAGE_B;
#pragma unroll
        for (int i = 0; i < 4; i++) {
            cpa16(st + stoff[i],            Ag + (long)i*32*INTER + k0);
            cpa16(st + DN_B_OFF + stoff[i], Bg + (long)i*32*INTER + k0);
        }
        CP_COMMIT();
    }

#define DN_BODY(SS)                                                            \
    {                                                                          \
        CP_WAIT(1);                                                            \
        __syncthreads();                                                       \
        if (j + 2 < nK) {                                                      \
            const int k0 = (j+2)*64;                                           \
            const uint32_t st = sb + (((SS)+2)%3)*DN_STAGE_B;                  \
            _Pragma("unroll")                                                  \
            for (int i = 0; i < 4; i++) {                                      \
                cpa16(st + stoff[i],            Ag + (long)i*32*INTER + k0);   \
                cpa16(st + DN_B_OFF + stoff[i], Bg + (long)i*32*INTER + k0);   \
            }                                                                  \
        }                                                                      \
        CP_COMMIT();                                                           \
        const uint32_t As = sb + (SS)*DN_STAGE_B;                              \
        const uint32_t Bs = As + DN_B_OFF;                                     \
        _Pragma("unroll")                                                      \
        for (int ks = 0; ks < 4; ks++) {                                       \
            uint32_t af[4][4], bf0[4], bf1[4];                                 \
            _Pragma("unroll")                                                  \
            for (int mi = 0; mi < 4; mi++)                                     \
                ldsm4(af[mi], As + browA + mi*2048 + akb_r[ks]);               \
            ldsm4(bf0, Bs + browB + bkb_r[ks]);                                \
            ldsm4(bf1, Bs + browB + 16*128 + bkb_r[ks]);                       \
            _Pragma("unroll")                                                  \
            for (int mi = 0; mi < 4; mi++) {                                   \
                _Pragma("unroll")                                              \
                for (int ni = 0; ni < 2; ni++)                                 \
                    mma_f16(acc[mi][ni], af[mi][0], af[mi][1], af[mi][2],      \
                            af[mi][3], bf0[ni*2], bf0[ni*2+1]);                \
                _Pragma("unroll")                                              \
                for (int ni = 0; ni < 2; ni++)                                 \
                    mma_f16(acc[mi][2+ni], af[mi][0], af[mi][1], af[mi][2],    \
                            af[mi][3], bf1[ni*2], bf1[ni*2+1]);                \
            }                                                                  \
        }                                                                      \
        j++;                                                                   \
    }

    {
        int j = 0;
        while (j + 3 <= nK) { DN_BODY(0); DN_BODY(1); DN_BODY(2); }
        DN_BODY(0); DN_BODY(1);   // 86 = 3*28 + 2
    }
#undef DN_BODY

#pragma unroll
    for (int mi = 0; mi < 4; mi++) {
#pragma unroll
        for (int ni = 0; ni < 4; ni++) {
            long r0 = bm + wm*64 + mi*16 + grp;
            long c0 = bn + wn*32 + ni*8 + tig*2;
            *(float2*)(C + r0*HID + c0)     = make_float2(acc[mi][ni][0], acc[mi][ni][1]);
            *(float2*)(C + (r0+8)*HID + c0) = make_float2(acc[mi][ni][2], acc[mi][ni][3]);
        }
    }
}

// ============================================================================
// Conversions + impacts finalize
// ============================================================================
#define NX4 ((long)MTOK*HID/4)      // 4194304
#define NW4 ((long)INTER*HID/4)     // 2818048

__global__ void __launch_bounds__(256)
cvt_main(const float4* __restrict__ X,  const float4* __restrict__ Wg,
         const float4* __restrict__ Wu,
         __half2* __restrict__ Xh, __half2* __restrict__ Wgh,
         __half2* __restrict__ Wuh, float* __restrict__ rowsq)
{
    long i = (long)blockIdx.x * 256 + threadIdx.x;
    const float4* src;
    __half2* dst;
    bool is_wu = false;
    if (i < NX4)            { src = X;  dst = Xh; }
    else if (i < NX4 + NW4) { src = Wg; dst = Wgh; i -= NX4; }
    else                    { src = Wu; dst = Wuh; i -= NX4 + NW4; is_wu = true; }

    float4 v = src[i];
    dst[2*i]   = __floats2half2_rn(v.x, v.y);
    dst[2*i+1] = __floats2half2_rn(v.z, v.w);

    if (is_wu) {
        float s = v.x*v.x + v.y*v.y + v.z*v.z + v.w*v.w;
#pragma unroll
        for (int off = 16; off > 0; off >>= 1)
            s += __shfl_xor_sync(0xffffffffu, s, off);
        if ((threadIdx.x & 31) == 0) {
            int row = (int)(i >> 9);
            atomicAdd(&rowsq[row], s);
        }
    }
}

__global__ void __launch_bounds__(256)
cvt_wd(const float4* __restrict__ Wd, __half2* __restrict__ Wdh)
{
    long i = (long)blockIdx.x * 256 + threadIdx.x;
    float4 v = Wd[i];
    Wdh[2*i]   = __floats2half2_rn(v.x, v.y);
    Wdh[2*i+1] = __floats2half2_rn(v.z, v.w);
}

__global__ void impacts_final(const float* __restrict__ spart, const float* __restrict__ rowsq,
                              float* __restrict__ out){
    int idx = blockIdx.x * 256 + threadIdx.x;
    if (idx >= BATCH * INTER) return;
    int i = idx % INTER;
    out[idx] = sqrtf(spart[idx] * rowsq[i]);
}

// ---------------- launch ----------------
extern "C" void kernel_launch(void* const* d_in, const int* in_sizes, int n_in,
                              void* d_out, int out_size)
{
    const float* X  = (const float*)d_in[0];
    const float* Wg = (const float*)d_in[1];
    const float* Wu = (const float*)d_in[2];
    const float* Wd = (const float*)d_in[3];
    float* out = (float*)d_out;

    __half *Xh, *Wgh, *Wuh, *Wdh, *inter;
    float *rsq, *spart;
    cudaGetSymbolAddress((void**)&Xh,  g_Xh);
    cudaGetSymbolAddress((void**)&Wgh, g_Wgh);
    cudaGetSymbolAddress((void**)&Wuh, g_Wuh);
    cudaGetSymbolAddress((void**)&Wdh, g_Wdh);
    cudaGetSymbolAddress((void**)&inter, g_inter);
    cudaGetSymbolAddress((void**)&rsq, g_rowsq);
    cudaGetSymbolAddress((void**)&spart, g_s);

    cudaFuncSetAttribute(gemm_gu,   cudaFuncAttributeMaxDynamicSharedMemorySize, GU_SMEM_BYTES);
    cudaFuncSetAttribute(gemm_down, cudaFuncAttributeMaxDynamicSharedMemorySize, DN_SMEM_BYTES);

    // side stream + events (created on the uncaptured correctness call)
    static cudaStream_t s2 = nullptr;
    static cudaEvent_t eRoot = nullptr, eG[4] = {nullptr,nullptr,nullptr,nullptr}, eDone = nullptr;
    if (!s2) {
        cudaStreamCreateWithFlags(&s2, cudaStreamNonBlocking);
        cudaEventCreateWithFlags(&eRoot, cudaEventDisableTiming);
        for (int g = 0; g < 4; g++) cudaEventCreateWithFlags(&eG[g], cudaEventDisableTiming);
        cudaEventCreateWithFlags(&eDone, cudaEventDisableTiming);
    }

    // zero accumulators
    cudaMemsetAsync(spart, 0, BATCH*INTER*sizeof(float));
    cudaMemsetAsync(rsq,   0, INTER*sizeof(float));

    // fork side stream
    cudaEventRecord(eRoot, 0);
    cudaStreamWaitEvent(s2, eRoot, 0);

    // side stream: Wd conversion (ready long before first down chunk)
    cvt_wd<<<(unsigned)(NW4/256), 256, 0, s2>>>((const float4*)Wd, (__half2*)Wdh);

    // main stream: X/Wg/Wu conversion (+ rowsq)
    long main4 = NX4 + 2*NW4;
    cvt_main<<<(unsigned)(main4/256), 256>>>(
        (const float4*)X, (const float4*)Wg, (const float4*)Wu,
        (__half2*)Xh, (__half2*)Wgh, (__half2*)Wuh, rsq);

    // gu chunks on main; matching down chunks on s2 gated by events.
    const unsigned GU_GRID = (INTER/64)*16;   // 1376
    const unsigned DN_GRID = (HID/128)*16;    // 256
    for (int g = 0; g < 4; g++) {
        gemm_gu<<<GU_GRID, 256, GU_SMEM_BYTES>>>(Xh, Wgh, Wuh, inter, spart, g);
        cudaEventRecord(eG[g], 0);
        cudaStreamWaitEvent(s2, eG[g], 0);
        gemm_down<<<DN_GRID, 256, DN_SMEM_BYTES, s2>>>(inter, Wdh, out, g);
    }

    // impacts on s2 (ordered after last down chunk & eG[3] -> spart complete)
    impacts_final<<<(BATCH*INTER + 255)/256, 256, 0, s2>>>(spart, rsq, out + OUT_ELEMS);
    cudaEventRecord(eDone, s2);

    // join
    cudaStreamWaitEvent(0, eDone, 0);
}

// round 17
// speedup vs baseline: 1.6430x; 1.6430x over previous
#include <cuda_runtime.h>
#include <cuda_fp16.h>
#include <cstdint>
#include <math.h>

#define BATCH 4
#define SEQ   2048
#define HID   2048
#define INTER 5504
#define MTOK  (BATCH*SEQ)            // 8192
#define OUT_ELEMS ((long)MTOK*HID)   // 16777216

// ---------------- scratch ----------------
__device__ __half g_Xh [(long)MTOK*HID];
__device__ __half g_Wgh[(long)INTER*HID];
__device__ __half g_Wuh[(long)INTER*HID];
__device__ __half g_Wdh[(long)HID*INTER];
__device__ __half g_inter[(long)MTOK*INTER];
__device__ float  g_rowsq[INTER];
__device__ float  g_s[BATCH*INTER];      // impacts accumulator (atomicAdd)

// ---------------- helpers ----------------
__device__ __forceinline__ uint32_t smem_u32(const void* p){
    uint32_t a;
    asm("{ .reg .u64 t; cvta.to.shared.u64 t, %1; cvt.u32.u64 %0, t; }" : "=r"(a) : "l"(p));
    return a;
}
__device__ __forceinline__ void cpa16(uint32_t dst, const void* src){
    asm volatile("cp.async.cg.shared.global [%0], [%1], 16;" :: "r"(dst), "l"(src));
}
__device__ __forceinline__ void ldsm4(uint32_t r[4], uint32_t addr){
    asm volatile("ldmatrix.sync.aligned.m8n8.x4.shared.b16 {%0,%1,%2,%3}, [%4];"
                 : "=r"(r[0]), "=r"(r[1]), "=r"(r[2]), "=r"(r[3]) : "r"(addr));
}
__device__ __forceinline__ void mma_f16(float c[4],
                                        uint32_t a0, uint32_t a1, uint32_t a2, uint32_t a3,
                                        uint32_t b0, uint32_t b1) {
    asm volatile(
        "mma.sync.aligned.m16n8k16.row.col.f32.f16.f16.f32 "
        "{%0,%1,%2,%3}, {%4,%5,%6,%7}, {%8,%9}, {%0,%1,%2,%3};"
        : "+f"(c[0]), "+f"(c[1]), "+f"(c[2]), "+f"(c[3])
        : "r"(a0), "r"(a1), "r"(a2), "r"(a3), "r"(b0), "r"(b1));
}
#define CP_COMMIT() asm volatile("cp.async.commit_group;" ::: "memory")
#define CP_WAIT(n)  asm volatile("cp.async.wait_group %0;" :: "n"(n) : "memory")

// 128B-row XOR swizzle (conflict-free)
#define SWZB(o) ((o) ^ (((o) >> 3) & 0x70))

// ============================================================================
// Fused gate/up GEMM + SwiGLU + impacts partial reduction.  (R13-proven)
// Block 128m x 64n, 8 warps (2m x 4n), warp 64m x 16n per mat.
// 3 stages x 32KB = 96KB -> 2 CTAs/SM. Mainloop unrolled by 3.
// ============================================================================
#define GU_STAGE_B 32768
#define GU_BG_OFF  16384
#define GU_BU_OFF  24576
#define GU_SMEM_BYTES (3*GU_STAGE_B)   // 98304

__global__ void __launch_bounds__(256,2)
gemm_gu(const __half* __restrict__ X, const __half* __restrict__ Wg,
        const __half* __restrict__ Wu, __half* __restrict__ inter,
        float* __restrict__ spart)
{
    extern __shared__ char smemc[];
    const uint32_t sb = smem_u32(smemc);

    const int tid  = threadIdx.x;
    const int wid  = tid >> 5;
    const int lane = tid & 31;
    const int grp  = lane >> 2;
    const int tig  = lane & 3;
    const int wm   = wid >> 2;    // 0..1
    const int wn   = wid & 3;     // 0..3

    const int NBN = INTER/64;     // 86
    const int GM  = 16;
    int bid = blockIdx.x;
    int g   = bid / (GM*NBN);
    int r   = bid % (GM*NBN);
    const long bm = (long)(g*GM + (r % GM)) * 128;
    const int  bn = (r / GM) * 64;

    const int ldr = tid >> 3;        // 0..31
    const int ldc = tid & 7;         // 0..7 (16B units)

    const __half* Ag = X  + (bm + ldr)*(long)HID + ldc*8;
    const __half* Gg = Wg + (long)(bn + ldr)*HID + ldc*8;
    const __half* Ug = Wu + (long)(bn + ldr)*HID + ldc*8;

    float acc_g[4][2][4], acc_u[4][2][4];
#pragma unroll
    for (int mi = 0; mi < 4; mi++)
#pragma unroll
        for (int ni = 0; ni < 2; ni++)
#pragma unroll
            for (int q = 0; q < 4; q++) { acc_g[mi][ni][q] = 0.f; acc_u[mi][ni][q] = 0.f; }

    uint32_t stoffA[4];
#pragma unroll
    for (int i = 0; i < 4; i++)
        stoffA[i] = SWZB((uint32_t)((ldr + 32*i)*128 + ldc*16));
    uint32_t stoffB[2];
#pragma unroll
    for (int i = 0; i < 2; i++)
        stoffB[i] = SWZB((uint32_t)((ldr + 32*i)*128 + ldc*16));

    // ldmatrix per-lane geometry (hoisted XOR terms)
    const uint32_t swzm = (lane & 7) * 16;
    const uint32_t browA = (wm*64 + (lane & 15)) * 128;
    const uint32_t akbe = ((lane >> 4) & 1) * 16;
    const uint32_t browB = (wn*16 + ((lane >> 4) & 1)*8 + (lane & 7)) * 128;
    const uint32_t bkbe = ((lane >> 3) & 1) * 16;
    uint32_t akb_r[4], bkb_r[4];
#pragma unroll
    for (int ks = 0; ks < 4; ks++) {
        akb_r[ks] = ((uint32_t)(ks*32) + akbe) ^ swzm;
        bkb_r[ks] = ((uint32_t)(ks*32) + bkbe) ^ swzm;
    }

    const int nK = HID/64;   // 32

    // preload chunks 0,1 into stages 0,1
#pragma unroll
    for (int p = 0; p < 2; p++) {
        const int k0 = p*64;
        const uint32_t st = sb + p*GU_STAGE_B;
#pragma unroll
        for (int i = 0; i < 4; i++)
            cpa16(st + stoffA[i], Ag + (long)i*32*HID + k0);
#pragma unroll
        for (int i = 0; i < 2; i++) {
            cpa16(st + GU_BG_OFF + stoffB[i], Gg + (long)i*32*HID + k0);
            cpa16(st + GU_BU_OFF + stoffB[i], Ug + (long)i*32*HID + k0);
        }
        CP_COMMIT();
    }

#define GU_BODY(SS)                                                            \
    {                                                                          \
        CP_WAIT(1);                                                            \
        __syncthreads();                                                       \
        if (j + 2 < nK) {                                                      \
            const int k0 = (j+2)*64;                                           \
            const uint32_t st = sb + (((SS)+2)%3)*GU_STAGE_B;                  \
            _Pragma("unroll")                                                  \
            for (int i = 0; i < 4; i++)                                        \
                cpa16(st + stoffA[i], Ag + (long)i*32*HID + k0);               \
            _Pragma("unroll")                                                  \
            for (int i = 0; i < 2; i++) {                                      \
                cpa16(st + GU_BG_OFF + stoffB[i], Gg + (long)i*32*HID + k0);   \
                cpa16(st + GU_BU_OFF + stoffB[i], Ug + (long)i*32*HID + k0);   \
            }                                                                  \
        }                                                                      \
        CP_COMMIT();                                                           \
        const uint32_t As = sb + (SS)*GU_STAGE_B;                              \
        const uint32_t Gs = As + GU_BG_OFF;                                    \
        const uint32_t Us = As + GU_BU_OFF;                                    \
        _Pragma("unroll")                                                      \
        for (int ks = 0; ks < 4; ks++) {                                       \
            uint32_t af[4][4], bg[4], bu[4];                                   \
            _Pragma("unroll")                                                  \
            for (int mi = 0; mi < 4; mi++)                                     \
                ldsm4(af[mi], As + browA + mi*2048 + akb_r[ks]);               \
            ldsm4(bg, Gs + browB + bkb_r[ks]);                                 \
            ldsm4(bu, Us + browB + bkb_r[ks]);                                 \
            _Pragma("unroll")                                                  \
            for (int mi = 0; mi < 4; mi++)                                     \
                _Pragma("unroll")                                              \
                for (int ni = 0; ni < 2; ni++) {                               \
                    mma_f16(acc_g[mi][ni], af[mi][0], af[mi][1], af[mi][2],    \
                            af[mi][3], bg[ni*2], bg[ni*2+1]);                  \
                    mma_f16(acc_u[mi][ni], af[mi][0], af[mi][1], af[mi][2],    \
                            af[mi][3], bu[ni*2], bu[ni*2+1]);                  \
                }                                                              \
        }                                                                      \
        j++;                                                                   \
    }

    {
        int j = 0;
        while (j + 3 <= nK) { GU_BODY(0); GU_BODY(1); GU_BODY(2); }
        // nK % 3 == 2 tail (32 = 3*10 + 2), enters with j % 3 == 0
        GU_BODY(0); GU_BODY(1);
    }
#undef GU_BODY

    // epilogue: inter = half( silu(g) * u );  colsum += o^2 for impacts
    float cs[2][2] = {{0.f,0.f},{0.f,0.f}};   // [ni][col in pair]
#pragma unroll
    for (int mi = 0; mi < 4; mi++) {
#pragma unroll
        for (int ni = 0; ni < 2; ni++) {
            long r0 = bm + wm*64 + mi*16 + grp;
            long c0 = bn + wn*16 + ni*8 + tig*2;
            float gv, uv; __half2 h;
            gv = acc_g[mi][ni][0]; uv = acc_u[mi][ni][0];
            float o0 = (gv / (1.f + __expf(-gv))) * uv;
            gv = acc_g[mi][ni][1]; uv = acc_u[mi][ni][1];
            float o1 = (gv / (1.f + __expf(-gv))) * uv;
            h = __floats2half2_rn(o0, o1);
            *(__half2*)(inter + r0*INTER + c0) = h;
            gv = acc_g[mi][ni][2]; uv = acc_u[mi][ni][2];
            float o2 = (gv / (1.f + __expf(-gv))) * uv;
            gv = acc_g[mi][ni][3]; uv = acc_u[mi][ni][3];
            float o3 = (gv / (1.f + __expf(-gv))) * uv;
            h = __floats2half2_rn(o2, o3);
            *(__half2*)(inter + (r0+8)*INTER + c0) = h;
            cs[ni][0] += o0*o0 + o2*o2;
            cs[ni][1] += o1*o1 + o3*o3;
        }
    }
    // reduce over the 8 row-lane-groups (lanes differing in bits 2..4)
#pragma unroll
    for (int off = 4; off < 32; off <<= 1) {
#pragma unroll
        for (int ni = 0; ni < 2; ni++) {
            cs[ni][0] += __shfl_xor_sync(0xffffffffu, cs[ni][0], off);
            cs[ni][1] += __shfl_xor_sync(0xffffffffu, cs[ni][1], off);
        }
    }
    if (grp == 0) {
        const int b = (int)(bm >> 11);          // bm / SEQ
        float* sp = spart + b*INTER;
#pragma unroll
        for (int ni = 0; ni < 2; ni++) {
            int c0 = bn + wn*16 + ni*8 + tig*2;
            atomicAdd(&sp[c0],   cs[ni][0]);
            atomicAdd(&sp[c0+1], cs[ni][1]);
        }
    }
}

// ============================================================================
// Down GEMM fp16 + ldmatrix (R10-proven): out = inter * Wd^T, K=5504.
// Block 128x128, warp 64x32; 3 stages x 32KB = 96KB -> 2 CTAs/SM.
// ============================================================================
#define DN_STAGE_B 32768
#define DN_B_OFF   16384
#define DN_SMEM_BYTES (3*DN_STAGE_B)   // 98304

__global__ void __launch_bounds__(256,2)
gemm_down(const __half* __restrict__ A, const __half* __restrict__ B, float* __restrict__ C)
{
    extern __shared__ char smemc[];
    const uint32_t sb = smem_u32(smemc);

    const int tid  = threadIdx.x;
    const int wid  = tid >> 5;
    const int lane = tid & 31;
    const int grp  = lane >> 2;
    const int tig  = lane & 3;
    const int wm   = wid >> 2;
    const int wn   = wid & 3;

    const int NBN = HID/128;   // 16
    const int GM  = 16;
    int bid = blockIdx.x;
    int g   = bid / (GM*NBN);
    int r   = bid % (GM*NBN);
    const long bm = (long)(g*GM + (r % GM)) * 128;
    const int  bn = (r / GM) * 128;

    const int ldr = tid >> 3;
    const int ldc = tid & 7;

    const __half* Ag = A + (bm + ldr)*(long)INTER + ldc*8;
    const __half* Bg = B + (long)(bn + ldr)*INTER + ldc*8;

    float acc[4][4][4];
#pragma unroll
    for (int mi = 0; mi < 4; mi++)
#pragma unroll
        for (int ni = 0; ni < 4; ni++)
#pragma unroll
            for (int q = 0; q < 4; q++) acc[mi][ni][q] = 0.f;

    uint32_t stoff[4];
#pragma unroll
    for (int i = 0; i < 4; i++)
        stoff[i] = SWZB((uint32_t)((ldr + 32*i)*128 + ldc*16));

    const uint32_t swzm = (lane & 7) * 16;
    const uint32_t browA = (wm*64 + (lane & 15)) * 128;
    const uint32_t akbe = ((lane >> 4) & 1) * 16;
    const uint32_t browB = (wn*32 + ((lane >> 4) & 1)*8 + (lane & 7)) * 128;
    const uint32_t bkbe = ((lane >> 3) & 1) * 16;
    uint32_t akb_r[4], bkb_r[4];
#pragma unroll
    for (int ks = 0; ks < 4; ks++) {
        akb_r[ks] = ((uint32_t)(ks*32) + akbe) ^ swzm;
        bkb_r[ks] = ((uint32_t)(ks*32) + bkbe) ^ swzm;
    }

    const int nK = INTER/64;   // 86

#pragma unroll
    for (int p = 0; p < 2; p++) {
        const int k0 = p*64;
        const uint32_t st = sb + p*DN_STAGE_B;
#pragma unroll
        for (int i = 0; i < 4; i++) {
            cpa16(st + stoff[i],            Ag + (long)i*32*INTER + k0);
            cpa16(st + DN_B_OFF + stoff[i], Bg + (long)i*32*INTER + k0);
        }
        CP_COMMIT();
    }

#define DN_BODY(SS)                                                            \
    {                                                                          \
        CP_WAIT(1);                                                            \
        __syncthreads();                                                       \
        if (j + 2 < nK) {                                                      \
            const int k0 = (j+2)*64;                                           \
            const uint32_t st = sb + (((SS)+2)%3)*DN_STAGE_B;                  \
            _Pragma("unroll")                                                  \
            for (int i = 0; i < 4; i++) {                                      \
                cpa16(st + stoff[i],            Ag + (long)i*32*INTER + k0);   \
                cpa16(st + DN_B_OFF + stoff[i], Bg + (long)i*32*INTER + k0);   \
            }                                                                  \
        }                                                                      \
        CP_COMMIT();                                                           \
        const uint32_t As = sb + (SS)*DN_STAGE_B;                              \
        const uint32_t Bs = As + DN_B_OFF;                                     \
        _Pragma("unroll")                                                      \
        for (int ks = 0; ks < 4; ks++) {                                       \
            uint32_t af[4][4], bf0[4], bf1[4];                                 \
            _Pragma("unroll")                                                  \
            for (int mi = 0; mi < 4; mi++)                                     \
                ldsm4(af[mi], As + browA + mi*2048 + akb_r[ks]);               \
            ldsm4(bf0, Bs + browB + bkb_r[ks]);                                \
            ldsm4(bf1, Bs + browB + 16*128 + bkb_r[ks]);                       \
            _Pragma("unroll")                                                  \
            for (int mi = 0; mi < 4; mi++) {                                   \
                _Pragma("unroll")                                              \
                for (int ni = 0; ni < 2; ni++)                                 \
                    mma_f16(acc[mi][ni], af[mi][0], af[mi][1], af[mi][2],      \
                            af[mi][3], bf0[ni*2], bf0[ni*2+1]);                \
                _Pragma("unroll")                                              \
                for (int ni = 0; ni < 2; ni++)                                 \
                    mma_f16(acc[mi][2+ni], af[mi][0], af[mi][1], af[mi][2],    \
                            af[mi][3], bf1[ni*2], bf1[ni*2+1]);                \
            }                                                                  \
        }                                                                      \
        j++;                                                                   \
    }

    {
        int j = 0;
        while (j + 3 <= nK) { DN_BODY(0); DN_BODY(1); DN_BODY(2); }
        // nK % 3 == 2 tail (86 = 3*28 + 2), enters with j % 3 == 0
        DN_BODY(0); DN_BODY(1);
    }
#undef DN_BODY

#pragma unroll
    for (int mi = 0; mi < 4; mi++) {
#pragma unroll
        for (int ni = 0; ni < 4; ni++) {
            long r0 = bm + wm*64 + mi*16 + grp;
            long c0 = bn + wn*32 + ni*8 + tig*2;
            *(float2*)(C + r0*HID + c0)     = make_float2(acc[mi][ni][0], acc[mi][ni][1]);
            *(float2*)(C + (r0+8)*HID + c0) = make_float2(acc[mi][ni][2], acc[mi][ni][3]);
        }
    }
}

// ============================================================================
// Conversion kernels.
// cvt_main: X, Wg, Wu fp32 -> fp16 (+ rowsq from Wu via warp-reduce atomics).
// cvt_wd:   Wd fp32 -> fp16 (side stream, overlapped with gemm_gu).
// ============================================================================
#define NX4 ((long)MTOK*HID/4)      // 4194304
#define NW4 ((long)INTER*HID/4)     // 2818048

__global__ void __launch_bounds__(256)
cvt_main(const float4* __restrict__ X,  const float4* __restrict__ Wg,
         const float4* __restrict__ Wu,
         __half2* __restrict__ Xh, __half2* __restrict__ Wgh,
         __half2* __restrict__ Wuh, float* __restrict__ rowsq)
{
    long i = (long)blockIdx.x * 256 + threadIdx.x;
    const float4* src;
    __half2* dst;
    bool is_wu = false;
    if (i < NX4)            { src = X;  dst = Xh; }
    else if (i < NX4 + NW4) { src = Wg; dst = Wgh; i -= NX4; }
    else                    { src = Wu; dst = Wuh; i -= NX4 + NW4; is_wu = true; }

    float4 v = src[i];
    dst[2*i]   = __floats2half2_rn(v.x, v.y);
    dst[2*i+1] = __floats2half2_rn(v.z, v.w);

    if (is_wu) {
        float s = v.x*v.x + v.y*v.y + v.z*v.z + v.w*v.w;
#pragma unroll
        for (int off = 16; off > 0; off >>= 1)
            s += __shfl_xor_sync(0xffffffffu, s, off);
        if ((threadIdx.x & 31) == 0) {
            int row = (int)(i >> 9);          // i*4 / 2048
            atomicAdd(&rowsq[row], s);
        }
    }
}

__global__ void __launch_bounds__(256)
cvt_wd(const float4* __restrict__ Wd, __half2* __restrict__ Wdh)
{
    long i = (long)blockIdx.x * 256 + threadIdx.x;
    float4 v = Wd[i];
    Wdh[2*i]   = __floats2half2_rn(v.x, v.y);
    Wdh[2*i+1] = __floats2half2_rn(v.z, v.w);
}

__global__ void impacts_final(const float* __restrict__ spart, const float* __restrict__ rowsq,
                              float* __restrict__ out){
    int idx = blockIdx.x * 256 + threadIdx.x;
    if (idx >= BATCH * INTER) return;
    int i = idx % INTER;
    out[idx] = sqrtf(spart[idx] * rowsq[i]);
}

// ---------------- launch ----------------
extern "C" void kernel_launch(void* const* d_in, const int* in_sizes, int n_in,
                              void* d_out, int out_size)
{
    const float* X  = (const float*)d_in[0];
    const float* Wg = (const float*)d_in[1];
    const float* Wu = (const float*)d_in[2];
    const float* Wd = (const float*)d_in[3];
    float* out = (float*)d_out;

    __half *Xh, *Wgh, *Wuh, *Wdh, *inter;
    float *rsq, *spart;
    cudaGetSymbolAddress((void**)&Xh,  g_Xh);
    cudaGetSymbolAddress((void**)&Wgh, g_Wgh);
    cudaGetSymbolAddress((void**)&Wuh, g_Wuh);
    cudaGetSymbolAddress((void**)&Wdh, g_Wdh);
    cudaGetSymbolAddress((void**)&inter, g_inter);
    cudaGetSymbolAddress((void**)&rsq, g_rowsq);
    cudaGetSymbolAddress((void**)&spart, g_s);

    cudaFuncSetAttribute(gemm_gu,   cudaFuncAttributeMaxDynamicSharedMemorySize, GU_SMEM_BYTES);
    cudaFuncSetAttribute(gemm_down, cudaFuncAttributeMaxDynamicSharedMemorySize, DN_SMEM_BYTES);

    // side stream + events, created once on the (uncaptured) correctness call
    static cudaStream_t s2 = nullptr;
    static cudaEvent_t eRoot = nullptr, eWd = nullptr, eGu = nullptr, eDone = nullptr;
    if (!s2) {
        cudaStreamCreateWithFlags(&s2, cudaStreamNonBlocking);
        cudaEventCreateWithFlags(&eRoot, cudaEventDisableTiming);
        cudaEventCreateWithFlags(&eWd,   cudaEventDisableTiming);
        cudaEventCreateWithFlags(&eGu,   cudaEventDisableTiming);
        cudaEventCreateWithFlags(&eDone, cudaEventDisableTiming);
    }

    // zero accumulators (memset nodes; graph-capturable)
    cudaMemsetAsync(spart, 0, BATCH*INTER*sizeof(float));
    cudaMemsetAsync(rsq,   0, INTER*sizeof(float));

    // fork side stream from main stream
    cudaEventRecord(eRoot, 0);
    cudaStreamWaitEvent(s2, eRoot, 0);

    // side stream: Wd conversion (overlaps cvt_main + gemm_gu on main stream)
    cvt_wd<<<(unsigned)(NW4/256), 256, 0, s2>>>((const float4*)Wd, (__half2*)Wdh);
    cudaEventRecord(eWd, s2);

    // main stream: X/Wg/Wu conversion (+ rowsq), then fused gate/up GEMM
    long main4 = NX4 + 2*NW4;                 // multiple of 256
    cvt_main<<<(unsigned)(main4/256), 256>>>(
        (const float4*)X, (const float4*)Wg, (const float4*)Wu,
        (__half2*)Xh, (__half2*)Wgh, (__half2*)Wuh, rsq);

    gemm_gu<<<(INTER/64)*(MTOK/128), 256, GU_SMEM_BYTES>>>(Xh, Wgh, Wuh, inter, spart);
    cudaEventRecord(eGu, 0);

    // side stream: impacts (needs spart+rsq, ready after gemm_gu) — overlaps gemm_down
    cudaStreamWaitEvent(s2, eGu, 0);
    impacts_final<<<(BATCH*INTER + 255)/256, 256, 0, s2>>>(spart, rsq, out + OUT_ELEMS);
    cudaEventRecord(eDone, s2);

    // main stream: down projection (needs Wdh from side stream)
    cudaStreamWaitEvent(0, eWd, 0);
    gemm_down<<<(HID/128)*(MTOK/128), 256, DN_SMEM_BYTES>>>(inter, Wdh, out);

    // join side stream back before capture ends
    cudaStreamWaitEvent(0, eDone, 0);
}